// round 15
// baseline (speedup 1.0000x reference)
#include <cuda_runtime.h>
#include <cuda_bf16.h>

// ---------------------------------------------------------------------------
// Fully fused trajectory GNN.
//   embed -> 5-step GRU encoder -> GAT (block-local, N=5) -> conf head
//   -> 6-step GRUCell decoder with mode-0 xy feedback -> traj
// One block = 8 samples = 40 nodes. 512 threads: j = tid&63 (hidden index),
// g = tid>>6 (local sample 0..7). All state + current-phase weights in SMEM.
// GEMMs use packed fp32x2 FMA with paired-k weight layout (LDS.64 everywhere).
// ---------------------------------------------------------------------------

#define H       64
#define NN      5     // nodes per sample
#define MM      5     // modes
#define TT      5     // input timesteps
#define TOUT    6
#define FD      10
#define SPB     8     // samples per block
#define NPB     40    // nodes per block
#define NTHREADS 512
#define WROW    193   // padded float2 row stride, 192-row weights
#define WROW1   65    // padded float2 row stride, 64-row weights

typedef unsigned long long u64;

struct __align__(16) Smem {
    float2 WA[32 * WROW];     // W_ih paired (enc, then dec)
    float2 WB[32 * WROW];     // W_hh paired (enc, then dec)
    float2 WC[32 * WROW1];    // gat_W -> conf_W1 -> out_W1 (paired)
    float  xe [NPB * H];      // x_emb(t) ; keeps t=4 for GAT
    float  hs [NPB * H];      // hidden state
    float  xl [NPB * H];      // xl / relu-hidden scratch
    float  din[NPB * H];      // decoder input
    float  xr [SPB * TT * NN * FD];   // raw x slice (2000)
    float  eW [FD * H];
    float  ow2[H * 10];       // out_W2 [k][c]
    float  cw2[H * MM];       // conf_W2 [k][m]
    float  pw [2 * H];        // proj_W [2][H]
    float  bihE[3*H], bhhE[3*H], bihD[3*H], bhhD[3*H];
    float  eb[H], gb[H], b1o[H], b1c[H], pb[H];
    float  attS[H], attD[H];
    float  b2o[12], b2c[8];
    float  as_[NPB], ad_[NPB];
    float  psum[SPB * 2 * NN * 2];   // [g][half][nn][{s,d}]
    float  w5 [NPB * NN];            // GAT weights / conf logits
    float  oxy[NPB * 2];
    int    msk[NPB];
};

__device__ __forceinline__ void ffma2(u64& d, u64 a, u64 b) {
    asm("fma.rn.f32x2 %0, %1, %2, %0;" : "+l"(d) : "l"(a), "l"(b));
}
__device__ __forceinline__ float red2(u64 a) {
    union { float2 f; u64 u; } t; t.u = a; return t.f.x + t.f.y;
}
__device__ __forceinline__ float fsig(float v) {
    return __fdividef(1.f, 1.f + __expf(-v));
}
__device__ __forceinline__ float ftanh_(float v) {
    return __fdividef(2.f, 1.f + __expf(-2.f * v)) - 1.f;
}
__device__ __forceinline__ float lrelu(float v) { return v > 0.f ? v : 0.2f * v; }
__device__ __forceinline__ u64 ldp(const float* p) {   // aligned pair load
    return *reinterpret_cast<const u64*>(p);
}

// torch-layout W[rows][64] -> paired: dst[kk*WROW + j] = {W[j][2kk], W[j][2kk+1]}
__device__ __forceinline__ void loadPairedRow(float2* dst, const float* src,
                                              int rows, int tid) {
    const float2* s2 = reinterpret_cast<const float2*>(src);
    for (int q = tid; q < rows * 32; q += NTHREADS) {
        int j = q >> 5, kk = q & 31;
        dst[kk * WROW + j] = s2[j * 32 + kk];   // coalesced read
    }
}
// k-major W[64][64] -> paired: dst[kk*WROW1 + j] = {W[2kk][j], W[2kk+1][j]}
__device__ __forceinline__ void loadPairedCol(float2* dst, const float* src, int tid) {
    for (int q = tid; q < 64 * 32; q += NTHREADS) {
        int kk = q >> 6, j = q & 63;
        dst[kk * WROW1 + j] = make_float2(src[(2 * kk) * 64 + j],
                                          (2 * kk + 1) < 64 ? src[(2 * kk + 1) * 64 + j] : 0.f);
    }
}
__device__ __forceinline__ void cpv(float* dst, const float* src, int n, int tid) {
    for (int i = tid; i < n; i += NTHREADS) dst[i] = src[i];
}

// GRU gates: xin = input activations [NPB][H]; produces hnew for 5 nodes of group g.
__device__ __forceinline__ void gru_step(const Smem* sm, const float* xin,
                                         const float* bih, const float* bhh,
                                         int j, int g, float hnew[NN]) {
    u64 aIr[NN], aIz[NN], aIn[NN], aHr[NN], aHz[NN], aHn[NN];
#pragma unroll
    for (int n = 0; n < NN; n++) { aIr[n]=0; aIz[n]=0; aIn[n]=0; aHr[n]=0; aHz[n]=0; aHn[n]=0; }
    const float2* WA = sm->WA;
    const float2* WB = sm->WB;
#pragma unroll 2
    for (int kk = 0; kk < 32; kk++) {
        u64 wir = ldp(&WA[kk * WROW +       j].x);
        u64 wiz = ldp(&WA[kk * WROW +  64 + j].x);
        u64 win = ldp(&WA[kk * WROW + 128 + j].x);
        u64 whr = ldp(&WB[kk * WROW +       j].x);
        u64 whz = ldp(&WB[kk * WROW +  64 + j].x);
        u64 whn = ldp(&WB[kk * WROW + 128 + j].x);
#pragma unroll
        for (int n = 0; n < NN; n++) {
            int ln = g * NN + n;
            u64 xv = ldp(&xin[ln * H + 2 * kk]);
            u64 hv = ldp(&sm->hs[ln * H + 2 * kk]);
            ffma2(aIr[n], wir, xv); ffma2(aIz[n], wiz, xv); ffma2(aIn[n], win, xv);
            ffma2(aHr[n], whr, hv); ffma2(aHz[n], whz, hv); ffma2(aHn[n], whn, hv);
        }
    }
#pragma unroll
    for (int n = 0; n < NN; n++) {
        float r  = fsig(red2(aIr[n]) + bih[j]      + red2(aHr[n]) + bhh[j]);
        float z  = fsig(red2(aIz[n]) + bih[64 + j] + red2(aHz[n]) + bhh[64 + j]);
        float nv = ftanh_(red2(aIn[n]) + bih[128 + j] +
                          r * (red2(aHn[n]) + bhh[128 + j]));
        float ho = sm->hs[(g * NN + n) * H + j];
        hnew[n] = (1.f - z) * nv + z * ho;
    }
}

// out[ln][j] = act( bias[j] + sum_k xin[ln][k] * WC[k][j] )  (WC paired, 64x64)
__device__ __forceinline__ void gemmC(const Smem* sm, const float* xin,
                                      const float* bias, float* out,
                                      int j, int g, bool relu_) {
    u64 acc[NN];
#pragma unroll
    for (int n = 0; n < NN; n++) acc[n] = 0;
    const float2* WC = sm->WC;
#pragma unroll 2
    for (int kk = 0; kk < 32; kk++) {
        u64 w = ldp(&WC[kk * WROW1 + j].x);
#pragma unroll
        for (int n = 0; n < NN; n++) {
            u64 xv = ldp(&xin[(g * NN + n) * H + 2 * kk]);
            ffma2(acc[n], w, xv);
        }
    }
#pragma unroll
    for (int n = 0; n < NN; n++) {
        float v = red2(acc[n]);
        if (bias) v += bias[j];
        if (relu_) v = fmaxf(v, 0.f);
        out[(g * NN + n) * H + j] = v;
    }
}

__global__ __launch_bounds__(NTHREADS, 1)
void traj_gnn_kernel(
    const float* __restrict__ x,
    const float* __restrict__ embed_W, const float* __restrict__ embed_b,
    const float* __restrict__ gat_W,   const float* __restrict__ gat_att_src,
    const float* __restrict__ gat_att_dst, const float* __restrict__ gat_b,
    const float* __restrict__ enc_Wih, const float* __restrict__ enc_Whh,
    const float* __restrict__ enc_bih, const float* __restrict__ enc_bhh,
    const float* __restrict__ dec_Wih, const float* __restrict__ dec_Whh,
    const float* __restrict__ dec_bih, const float* __restrict__ dec_bhh,
    const float* __restrict__ out_W1,  const float* __restrict__ out_b1,
    const float* __restrict__ out_W2,  const float* __restrict__ out_b2,
    const float* __restrict__ proj_W,  const float* __restrict__ proj_b,
    const float* __restrict__ conf_W1, const float* __restrict__ conf_b1,
    const float* __restrict__ conf_W2, const float* __restrict__ conf_b2,
    float* __restrict__ out, long long conf_base)
{
    extern __shared__ char smem_raw[];
    Smem* sm = reinterpret_cast<Smem*>(smem_raw);

    const int tid  = threadIdx.x;
    const int j    = tid & 63;
    const int g    = tid >> 6;
    const int lane = tid & 31;
    const int half = j >> 5;
    const int b0   = blockIdx.x * SPB;

    // ---------------- phase 1: loads ----------------
    loadPairedRow(sm->WA, enc_Wih, 192, tid);
    loadPairedRow(sm->WB, enc_Whh, 192, tid);
    loadPairedCol(sm->WC, gat_W, tid);
    cpv(sm->xr, x + (long long)b0 * (TT * NN * FD), SPB * TT * NN * FD, tid);
    cpv(sm->eW, embed_W, FD * H, tid);
    cpv(sm->ow2, out_W2, H * 10, tid);
    cpv(sm->cw2, conf_W2, H * MM, tid);
    cpv(sm->pw, proj_W, 2 * H, tid);
    cpv(sm->bihE, enc_bih, 192, tid);  cpv(sm->bhhE, enc_bhh, 192, tid);
    cpv(sm->bihD, dec_bih, 192, tid);  cpv(sm->bhhD, dec_bhh, 192, tid);
    cpv(sm->eb, embed_b, H, tid);      cpv(sm->gb, gat_b, H, tid);
    cpv(sm->b1o, out_b1, H, tid);      cpv(sm->b1c, conf_b1, H, tid);
    cpv(sm->pb, proj_b, H, tid);
    cpv(sm->attS, gat_att_src, H, tid); cpv(sm->attD, gat_att_dst, H, tid);
    cpv(sm->b2o, out_b2, 10, tid);     cpv(sm->b2c, conf_b2, MM, tid);
    for (int i = tid; i < NPB * H; i += NTHREADS) sm->hs[i] = 0.f;
    for (int i = tid; i < NPB; i += NTHREADS) {
        int smp = i / NN, nn = i % NN;
        const float* p = &sm->xr[0];   // not yet synced; read from global instead
        float s = 0.f;
        long long base = ((long long)(b0 + smp) * TT + (TT - 1)) * NN * FD + nn * FD;
#pragma unroll
        for (int f = 0; f < 6; f++) s += x[base + f];
        sm->msk[i] = (s != 0.f);
        (void)p;
    }
    __syncthreads();

    // ---------------- phase 2: encoder ----------------
    for (int t = 0; t < TT; t++) {
#pragma unroll
        for (int nn = 0; nn < NN; nn++) {
            int base = (g * (TT * NN) + t * NN + nn) * FD;
            float v = sm->eb[j];
#pragma unroll
            for (int f = 0; f < FD; f++) v += sm->xr[base + f] * sm->eW[f * H + j];
            sm->xe[(g * NN + nn) * H + j] = v;
        }
        __syncthreads();
        float hn[NN];
        gru_step(sm, sm->xe, sm->bihE, sm->bhhE, j, g, hn);
        __syncthreads();
#pragma unroll
        for (int nn = 0; nn < NN; nn++) sm->hs[(g * NN + nn) * H + j] = hn[nn];
    }
    __syncthreads();   // hs = h_enc; xe holds t=4 embeddings

    // ---------------- phase 3: GAT ----------------
    gemmC(sm, sm->xe, nullptr, sm->xl, j, g, false);
    __syncthreads();
    {   // a_s, a_d via warp + 2-stage reduce
        float ps[NN], pd[NN];
#pragma unroll
        for (int nn = 0; nn < NN; nn++) {
            float v = sm->xl[(g * NN + nn) * H + j];
            ps[nn] = v * sm->attS[j];
            pd[nn] = v * sm->attD[j];
        }
#pragma unroll
        for (int off = 16; off > 0; off >>= 1) {
#pragma unroll
            for (int nn = 0; nn < NN; nn++) {
                ps[nn] += __shfl_xor_sync(0xffffffffu, ps[nn], off);
                pd[nn] += __shfl_xor_sync(0xffffffffu, pd[nn], off);
            }
        }
        if (lane == 0) {
#pragma unroll
            for (int nn = 0; nn < NN; nn++) {
                sm->psum[((g * 2 + half) * NN + nn) * 2 + 0] = ps[nn];
                sm->psum[((g * 2 + half) * NN + nn) * 2 + 1] = pd[nn];
            }
        }
    }
    __syncthreads();
    if (j < NN) {
        int ln = g * NN + j;
        sm->as_[ln] = sm->psum[((g * 2 + 0) * NN + j) * 2 + 0] +
                      sm->psum[((g * 2 + 1) * NN + j) * 2 + 0];
        sm->ad_[ln] = sm->psum[((g * 2 + 0) * NN + j) * 2 + 1] +
                      sm->psum[((g * 2 + 1) * NN + j) * 2 + 1];
    }
    __syncthreads();
    if (j < NN) {   // per-dst softmax over 5 srcs
        int d = j, lnd = g * NN + d;
        float adv = sm->ad_[lnd];
        int md = sm->msk[lnd];
        float alpha[NN], amax = -3.0e38f;
#pragma unroll
        for (int s = 0; s < NN; s++) {
            bool valid = (s == d) || (md && sm->msk[g * NN + s]);
            float a = valid ? lrelu(sm->as_[g * NN + s] + adv) : -1e30f;
            alpha[s] = a;
            amax = fmaxf(amax, a);
        }
        float e[NN], den = 0.f;
#pragma unroll
        for (int s = 0; s < NN; s++) { e[s] = __expf(alpha[s] - amax); den += e[s]; }
        float inv = __fdividef(1.f, den);
#pragma unroll
        for (int s = 0; s < NN; s++) sm->w5[lnd * NN + s] = e[s] * inv;
    }
    __syncthreads();
#pragma unroll
    for (int d = 0; d < NN; d++) {   // h_final = h_enc + gat_out
        float acc = sm->gb[j];
#pragma unroll
        for (int s = 0; s < NN; s++)
            acc += sm->w5[(g * NN + d) * NN + s] * sm->xl[(g * NN + s) * H + j];
        sm->hs[(g * NN + d) * H + j] += acc;
    }
    __syncthreads();

    // ---------------- phase 4: conf head (before decoder clobbers hs) -------
    loadPairedCol(sm->WC, conf_W1, tid);
    __syncthreads();
    gemmC(sm, sm->hs, sm->b1c, sm->xl, j, g, true);
    __syncthreads();
    if (j < 25) {
        int nn = j / MM, m = j % MM, ln = g * NN + nn;
        float a0 = 0.f, a1 = 0.f;
        const float* xb = &sm->xl[ln * H];
#pragma unroll
        for (int k = 0; k < H; k += 2) {
            a0 += xb[k]     * sm->cw2[k * MM + m];
            a1 += xb[k + 1] * sm->cw2[(k + 1) * MM + m];
        }
        sm->w5[ln * NN + m] = sm->b2c[m] + a0 + a1;
    }
    __syncthreads();
    if (j < NN) {
        int nn = j, ln = g * NN + nn;
        float mx = -3.0e38f;
#pragma unroll
        for (int m = 0; m < MM; m++) mx = fmaxf(mx, sm->w5[ln * NN + m]);
        float e[MM], den = 0.f;
#pragma unroll
        for (int m = 0; m < MM; m++) { e[m] = __expf(sm->w5[ln * NN + m] - mx); den += e[m]; }
        float inv = __fdividef(1.f, den);
        long long b = b0 + g;
#pragma unroll
        for (int m = 0; m < MM; m++)
            out[conf_base + (b * MM + m) * NN + nn] = e[m] * inv;
    }
    __syncthreads();

    // ---------------- phase 5: decoder ----------------
    loadPairedRow(sm->WA, dec_Wih, 192, tid);
    loadPairedRow(sm->WB, dec_Whh, 192, tid);
    loadPairedCol(sm->WC, out_W1, tid);
#pragma unroll
    for (int nn = 0; nn < NN; nn++) {
        int base = (g * (TT * NN) + (TT - 1) * NN + nn) * FD;
        float x0 = sm->xr[base], x1 = sm->xr[base + 1];
        sm->din[(g * NN + nn) * H + j] = sm->pb[j] + x0 * sm->pw[j] + x1 * sm->pw[H + j];
    }
    __syncthreads();

    for (int t = 0; t < TOUT; t++) {
        float hn[NN];
        gru_step(sm, sm->din, sm->bihD, sm->bhhD, j, g, hn);
        __syncthreads();
#pragma unroll
        for (int nn = 0; nn < NN; nn++) sm->hs[(g * NN + nn) * H + j] = hn[nn];
        __syncthreads();
        gemmC(sm, sm->hs, sm->b1o, sm->xl, j, g, true);   // relu hidden
        __syncthreads();
        if (j < 50) {
            int nn = j / 10, c = j % 10, ln = g * NN + nn;
            float a0 = 0.f, a1 = 0.f;
            const float* xb = &sm->xl[ln * H];
#pragma unroll
            for (int k = 0; k < H; k += 2) {
                a0 += xb[k]     * sm->ow2[k * 10 + c];
                a1 += xb[k + 1] * sm->ow2[(k + 1) * 10 + c];
            }
            float o = sm->b2o[c] + a0 + a1;
            int m = c % MM, xy = c / MM;
            long long b = b0 + g;
            out[((b * MM + m) * NN + nn) * (TOUT * 2) + t * 2 + xy] = o;
            if (c == 0) sm->oxy[ln * 2 + 0] = o;
            if (c == 5) sm->oxy[ln * 2 + 1] = o;
        }
        __syncthreads();
#pragma unroll
        for (int nn = 0; nn < NN; nn++) {
            int ln = g * NN + nn;
            sm->din[ln * H + j] = sm->pb[j] + sm->oxy[ln * 2] * sm->pw[j]
                                            + sm->oxy[ln * 2 + 1] * sm->pw[H + j];
        }
        __syncthreads();
    }
}

extern "C" void kernel_launch(void* const* d_in, const int* in_sizes, int n_in,
                              void* d_out, int out_size) {
    const float* x        = (const float*)d_in[0];
    const float* embed_W  = (const float*)d_in[1];
    const float* embed_b  = (const float*)d_in[2];
    const float* gat_W    = (const float*)d_in[3];
    const float* att_src  = (const float*)d_in[4];
    const float* att_dst  = (const float*)d_in[5];
    const float* gat_b    = (const float*)d_in[6];
    const float* enc_Wih  = (const float*)d_in[7];
    const float* enc_Whh  = (const float*)d_in[8];
    const float* enc_bih  = (const float*)d_in[9];
    const float* enc_bhh  = (const float*)d_in[10];
    const float* dec_Wih  = (const float*)d_in[11];
    const float* dec_Whh  = (const float*)d_in[12];
    const float* dec_bih  = (const float*)d_in[13];
    const float* dec_bhh  = (const float*)d_in[14];
    const float* out_W1   = (const float*)d_in[15];
    const float* out_b1   = (const float*)d_in[16];
    const float* out_W2   = (const float*)d_in[17];
    const float* out_b2   = (const float*)d_in[18];
    const float* proj_W   = (const float*)d_in[19];
    const float* proj_b   = (const float*)d_in[20];
    const float* conf_W1  = (const float*)d_in[21];
    const float* conf_b1  = (const float*)d_in[22];
    const float* conf_W2  = (const float*)d_in[23];
    const float* conf_b2  = (const float*)d_in[24];

    int B = in_sizes[0] / (TT * NN * FD);      // 32768
    long long conf_base = (long long)B * MM * NN * TOUT * 2;   // traj elements
    int blocks = B / SPB;
    size_t smem = sizeof(Smem);

    cudaFuncSetAttribute(traj_gnn_kernel,
                         cudaFuncAttributeMaxDynamicSharedMemorySize, (int)smem);

    traj_gnn_kernel<<<blocks, NTHREADS, smem>>>(
        x, embed_W, embed_b, gat_W, att_src, att_dst, gat_b,
        enc_Wih, enc_Whh, enc_bih, enc_bhh,
        dec_Wih, dec_Whh, dec_bih, dec_bhh,
        out_W1, out_b1, out_W2, out_b2, proj_W, proj_b,
        conf_W1, conf_b1, conf_W2, conf_b2,
        (float*)d_out, conf_base);
}